// round 14
// baseline (speedup 1.0000x reference)
#include <cuda_runtime.h>
#include <cstdint>
#include <cstddef>

#define TSTEPS 511

__device__ float g_GI[TSTEPS * 256 * 768];   // ~402MB scratch, permuted gi
__device__ double g_loss[256];               // per (cluster,rank,warp) partials

// ---- packed fp32x2 helpers ----
__device__ __forceinline__ void ffma2(unsigned long long& d, unsigned long long a, unsigned long long b) {
  asm("fma.rn.f32x2 %0, %1, %2, %0;" : "+l"(d) : "l"(a), "l"(b));
}
__device__ __forceinline__ float plo(unsigned long long v) { return __uint_as_float((unsigned)v); }
__device__ __forceinline__ float phi(unsigned long long v) { return __uint_as_float((unsigned)(v >> 32)); }
__device__ __forceinline__ unsigned long long pk2(float lo, float hi) {
  return ((unsigned long long)__float_as_uint(hi) << 32) | (unsigned long long)__float_as_uint(lo);
}
__device__ __forceinline__ float pred(unsigned long long v) { return plo(v) + phi(v); }

// ========================= Phase 1: gi = x @ W_ih^T + biases =========================
__global__ __launch_bounds__(256) void gi_kernel(
    const float* __restrict__ x, const float* __restrict__ W_ih,
    const float* __restrict__ b_ih, const float* __restrict__ b_hh)
{
  extern __shared__ float sm[];
  float* Xs = sm;               // [128][132]
  float* Ws = sm + 128 * 132;   // [64][132]
  const int tid = threadIdx.x;
  const int m0 = blockIdx.x * 128;
  const int n0 = blockIdx.y * 64;

  const float4* xg = (const float4*)x;
  for (int i = tid; i < 4096; i += 256) {
    int row = i >> 5, c4 = i & 31;
    float4 v = xg[(size_t)(m0 + row) * 32 + c4];
    *(float4*)&Xs[row * 132 + c4 * 4] = v;
  }
  const float4* wg = (const float4*)W_ih;
  for (int i = tid; i < 2048; i += 256) {
    int row = i >> 5, c4 = i & 31;
    float4 v = wg[(size_t)(n0 + row) * 32 + c4];
    *(float4*)&Ws[row * 132 + c4 * 4] = v;
  }
  __syncthreads();

  const int tx = tid & 15, ty = tid >> 4;
  unsigned long long acc[8][4];
  #pragma unroll
  for (int i = 0; i < 8; i++)
    #pragma unroll
    for (int j = 0; j < 4; j++) acc[i][j] = 0ull;

  #pragma unroll 2
  for (int k = 0; k < 128; k += 4) {
    ulonglong2 xv[8], wv[4];
    #pragma unroll
    for (int i = 0; i < 8; i++) xv[i] = *(const ulonglong2*)&Xs[(ty + i * 16) * 132 + k];
    #pragma unroll
    for (int j = 0; j < 4; j++) wv[j] = *(const ulonglong2*)&Ws[(tx + j * 16) * 132 + k];
    #pragma unroll
    for (int i = 0; i < 8; i++)
      #pragma unroll
      for (int j = 0; j < 4; j++) {
        ffma2(acc[i][j], xv[i].x, wv[j].x);
        ffma2(acc[i][j], xv[i].y, wv[j].y);
      }
  }

  #pragma unroll
  for (int j = 0; j < 4; j++) {
    int n = n0 + tx + j * 16;
    int p = n >> 8, ln = n & 63, rk = (n >> 6) & 3;
    float bias = b_ih[n] + (p < 2 ? b_hh[n] : 0.f);
    int gl = p * 64 + ln;
    #pragma unroll
    for (int i = 0; i < 8; i++) {
      int m = m0 + ty + i * 16;
      int t = m >> 8, b = m & 255;
      size_t addr = (size_t)((((t * 32 + (b >> 3)) * 4 + rk) * 8 + (b & 7))) * 192 + gl;
      g_GI[addr] = pred(acc[i][j]) + bias;
    }
  }
}

// ========================= Phase 2: recurrent scan (512 threads, K-split warps) =========================
__device__ __forceinline__ void stcl(uint32_t addr, uint32_t rk, float v) {
  uint32_t ra;
  asm volatile("mapa.shared::cluster.u32 %0, %1, %2;" : "=r"(ra) : "r"(addr), "r"(rk));
  asm volatile("st.shared::cluster.f32 [%0], %1;" :: "r"(ra), "f"(v) : "memory");
}

// smem float offsets
#define WS_OFF  0       // [192][264] W_hh slice, k-major, pitch 264 (bank-spread for K-split lanes)
#define H_OFF   50688   // 2 x [8][260] double-buffered full h
#define GI_OFF  54848   // [8][192] current gi (r,z overlaid with gh after GEMM)
#define GHN_OFF 56384   // [8][64] gh n-gate
#define BHN_OFF 56896   // [64]
#define WD_OFF  56960   // [256]
#define SM2_FLOATS 57216  // 228864 bytes

__global__ __launch_bounds__(512, 1) __cluster_dims__(4, 1, 1)
void rnn_kernel(const float* __restrict__ gt, const float* __restrict__ W_hh,
                const float* __restrict__ b_hh, const float* __restrict__ W_dec,
                const float* __restrict__ b_dec)
{
  extern __shared__ float sh[];
  float* Ws    = sh + WS_OFF;
  float* Hbuf  = sh + H_OFF;
  float* giS   = sh + GI_OFF;
  float* ghN   = sh + GHN_OFF;
  float* bhhnS = sh + BHN_OFF;
  float* wdecS = sh + WD_OFF;

  const int tid = threadIdx.x;
  const int warp = tid >> 5, lane = tid & 31;
  uint32_t rank; asm("mov.u32 %0, %%cluster_ctarank;" : "=r"(rank));
  const int cl = blockIdx.x >> 2;

  // W_hh slice: local gate gl = p*64+ln  <->  global row p*256+rank*64+ln ; pitch 264
  for (int i = tid; i < 12288; i += 512) {
    int j = i >> 6, c4 = i & 63;
    int p = j >> 6, ln = j & 63;
    float4 v = *(const float4*)&W_hh[(size_t)(p * 256 + (int)rank * 64 + ln) * 256 + c4 * 4];
    *(float4*)&Ws[j * 264 + c4 * 4] = v;
  }
  if (tid < 64) bhhnS[tid] = b_hh[512 + (int)rank * 64 + tid];
  if (tid < 256) wdecS[tid] = W_dec[tid];
  for (int i = tid; i < 4160; i += 512) Hbuf[i] = 0.f;
  {
    const float* src = g_GI + (size_t)(cl * 4 + (int)rank) * 1536;
    giS[tid] = src[tid]; giS[tid + 512] = src[tid + 512]; giS[tid + 1024] = src[tid + 1024];
  }
  const float bdec = b_dec[0];
  double lacc = 0.0;
  __syncthreads();
  asm volatile("barrier.cluster.arrive.aligned;" ::: "memory");
  asm volatile("barrier.cluster.wait.aligned;" ::: "memory");

  // Mapping: warp covers 4 gate-triples x 4 brow-pairs, K split by lane bit 4.
  // lane = khalf*16 + bp*4 + ts ; jt = warp*4 + ts ; K chunks: k = i*8 + khalf*4
  const int ts = lane & 3;
  const int bp = (lane >> 2) & 3;
  const int khalf = lane >> 4;
  const int jt = (warp << 2) + ts;           // triple 0..63
  const int b0 = bp << 1;                    // brows b0, b0+1
  const int g0 = jt * 3;                     // gates g0..g0+2
  const int koff = khalf << 2;
  const float* W0 = Ws + g0 * 264 + koff;
  const float* W1 = W0 + 264;
  const float* W2 = W0 + 528;

  for (int s = 0; s < TSTEPS; s++) {
    const float* Hr = Hbuf + (s & 1) * 2080;
    float* Hw = Hbuf + ((s + 1) & 1) * 2080;

    float gtv = 0.f;
    if (warp < 2) gtv = gt[(s + 1) * 256 + (cl << 3) + ((int)rank << 1) + warp];

    float p0, p1, p2;
    if (s + 1 < TSTEPS) {
      const float* ns = g_GI + (size_t)(((s + 1) * 32 + cl) * 4 + (int)rank) * 1536;
      p0 = ns[tid]; p1 = ns[tid + 512]; p2 = ns[tid + 1024];
    }

    // ---- GEMM: each half-warp does half of K; 6 packed accums ----
    unsigned long long a00 = 0ull, a01 = 0ull, a02 = 0ull;
    unsigned long long a10 = 0ull, a11 = 0ull, a12 = 0ull;

    const float* H0 = Hr + b0 * 260 + koff;
    const float* H1 = H0 + 260;
    #pragma unroll 8
    for (int i = 0; i < 32; i++) {
      int k = i << 3;
      ulonglong2 h0 = *(const ulonglong2*)(H0 + k);
      ulonglong2 h1 = *(const ulonglong2*)(H1 + k);
      ulonglong2 w0 = *(const ulonglong2*)(W0 + k);
      ulonglong2 w1 = *(const ulonglong2*)(W1 + k);
      ulonglong2 w2 = *(const ulonglong2*)(W2 + k);
      ffma2(a00, h0.x, w0.x); ffma2(a00, h0.y, w0.y);
      ffma2(a01, h0.x, w1.x); ffma2(a01, h0.y, w1.y);
      ffma2(a02, h0.x, w2.x); ffma2(a02, h0.y, w2.y);
      ffma2(a10, h1.x, w0.x); ffma2(a10, h1.y, w0.y);
      ffma2(a11, h1.x, w1.x); ffma2(a11, h1.y, w1.y);
      ffma2(a12, h1.x, w2.x); ffma2(a12, h1.y, w2.y);
    }
    float f00 = pred(a00), f01 = pred(a01), f02 = pred(a02);
    float f10 = pred(a10), f11 = pred(a11), f12 = pred(a12);
    // combine K halves (partner = lane ^ 16, same (jt,bp))
    f00 += __shfl_xor_sync(0xffffffffu, f00, 16);
    f01 += __shfl_xor_sync(0xffffffffu, f01, 16);
    f02 += __shfl_xor_sync(0xffffffffu, f02, 16);
    f10 += __shfl_xor_sync(0xffffffffu, f10, 16);
    f11 += __shfl_xor_sync(0xffffffffu, f11, 16);
    f12 += __shfl_xor_sync(0xffffffffu, f12, 16);

    if (khalf == 0) {
      if (g0     < 128) giS[b0 * 192 + g0    ] += f00; else ghN[(b0 << 6) + g0     - 128] = f00;
      if (g0 + 1 < 128) giS[b0 * 192 + g0 + 1] += f01; else ghN[(b0 << 6) + g0 + 1 - 128] = f01;
      if (g0 + 2 < 128) giS[b0 * 192 + g0 + 2] += f02; else ghN[(b0 << 6) + g0 + 2 - 128] = f02;
      if (g0     < 128) giS[(b0 + 1) * 192 + g0    ] += f10; else ghN[((b0 + 1) << 6) + g0     - 128] = f10;
      if (g0 + 1 < 128) giS[(b0 + 1) * 192 + g0 + 1] += f11; else ghN[((b0 + 1) << 6) + g0 + 1 - 128] = f11;
      if (g0 + 2 < 128) giS[(b0 + 1) * 192 + g0 + 2] += f12; else ghN[((b0 + 1) << 6) + g0 + 2 - 128] = f12;
    }
    __syncthreads();

    // ---- gates + h_new: 512 threads, 1 element each (cols [rank*64, rank*64+64)) ----
    {
      int b = tid >> 6, c = tid & 63;
      int colb = ((int)rank << 6) + c;
      float pr  = giS[b * 192 + c];
      float pz  = giS[b * 192 + 64 + c];
      float gin = giS[b * 192 + 128 + c];
      float ghn = ghN[(b << 6) + c] + bhhnS[c];
      float hp  = Hr[b * 260 + colb];
      float rr = __fdividef(1.f, 1.f + __expf(-pr));
      float zz = __fdividef(1.f, 1.f + __expf(-pz));
      float e2 = __expf(2.f * fmaf(rr, ghn, gin));
      float nn = 1.f - __fdividef(2.f, e2 + 1.f);
      float hv = (1.f - zz) * nn + zz * hp;
      float* dst = &Hw[b * 260 + colb];
      dst[0] = hv;
      uint32_t a = (uint32_t)__cvta_generic_to_shared(dst);
      stcl(a, (rank + 1) & 3, hv);
      stcl(a, (rank + 2) & 3, hv);
      stcl(a, (rank + 3) & 3, hv);
    }
    __syncthreads();
    asm volatile("barrier.cluster.arrive.aligned;" ::: "memory");
    if (s + 1 < TSTEPS) {  // stage next gi inside the arrive->wait window
      giS[tid] = p0; giS[tid + 512] = p1; giS[tid + 1024] = p2;
    }
    asm volatile("barrier.cluster.wait.aligned;" ::: "memory");

    // ---- decode + BCE: CTA rank handles local brows {2r, 2r+1} ----
    if (warp < 2) {
      const float* hrow = Hw + (((int)rank << 1) + warp) * 260;
      float part = 0.f;
      #pragma unroll
      for (int q = 0; q < 8; q++) part = fmaf(hrow[lane + q * 32], wdecS[lane + q * 32], part);
      #pragma unroll
      for (int o = 16; o > 0; o >>= 1) part += __shfl_xor_sync(0xffffffffu, part, o);
      if (lane == 0) {
        float L = part + bdec;
        float tl = log1pf(expf(-fabsf(L)));
        float lsp = fminf(L, 0.f) - tl;
        float lsm = fminf(-L, 0.f) - tl;
        lacc -= (double)(gtv * lsp + (1.f - gtv) * lsm);
      }
    }
  }

  if (warp < 2 && lane == 0)
    g_loss[(cl << 3) + ((int)rank << 1) + warp] = lacc;
}

// ========================= Phase 3: deterministic reduce =========================
__global__ void reduce_kernel(float* out) {
  double s = 0.0;
  for (int i = 0; i < 256; i++) s += g_loss[i];
  out[0] = (float)s;
}

extern "C" void kernel_launch(void* const* d_in, const int* in_sizes, int n_in,
                              void* d_out, int out_size) {
  (void)in_sizes; (void)n_in; (void)out_size;
  const float* x     = (const float*)d_in[0];
  const float* gt    = (const float*)d_in[1];
  const float* W_ih  = (const float*)d_in[2];
  const float* W_hh  = (const float*)d_in[3];
  const float* b_ih  = (const float*)d_in[4];
  const float* b_hh  = (const float*)d_in[5];
  const float* W_dec = (const float*)d_in[6];
  const float* b_dec = (const float*)d_in[7];

  cudaFuncSetAttribute(gi_kernel,  cudaFuncAttributeMaxDynamicSharedMemorySize, 101376);
  cudaFuncSetAttribute(rnn_kernel, cudaFuncAttributeMaxDynamicSharedMemorySize, SM2_FLOATS * 4);

  dim3 g1(1022, 12);
  gi_kernel<<<g1, 256, 101376>>>(x, W_ih, b_ih, b_hh);
  rnn_kernel<<<128, 512, SM2_FLOATS * 4>>>(gt, W_hh, b_hh, W_dec, b_dec);
  reduce_kernel<<<1, 1>>>((float*)d_out);
}

// round 15
// speedup vs baseline: 1.6652x; 1.6652x over previous
#include <cuda_runtime.h>
#include <cstdint>
#include <cstddef>

#define TSTEPS 511

__device__ float g_GI[TSTEPS * 256 * 768];   // ~402MB scratch, permuted gi
__device__ double g_loss[256];               // per (cluster,rank,warp) partials

// ---- packed fp32x2 helpers ----
__device__ __forceinline__ void ffma2(unsigned long long& d, unsigned long long a, unsigned long long b) {
  asm("fma.rn.f32x2 %0, %1, %2, %0;" : "+l"(d) : "l"(a), "l"(b));
}
__device__ __forceinline__ float plo(unsigned long long v) { return __uint_as_float((unsigned)v); }
__device__ __forceinline__ float phi(unsigned long long v) { return __uint_as_float((unsigned)(v >> 32)); }
__device__ __forceinline__ unsigned long long pk2(float lo, float hi) {
  return ((unsigned long long)__float_as_uint(hi) << 32) | (unsigned long long)__float_as_uint(lo);
}
__device__ __forceinline__ float pred(unsigned long long v) { return plo(v) + phi(v); }

// ========================= Phase 1: gi = x @ W_ih^T + biases =========================
__global__ __launch_bounds__(256) void gi_kernel(
    const float* __restrict__ x, const float* __restrict__ W_ih,
    const float* __restrict__ b_ih, const float* __restrict__ b_hh)
{
  extern __shared__ float sm[];
  float* Xs = sm;               // [128][132]
  float* Ws = sm + 128 * 132;   // [64][132]
  const int tid = threadIdx.x;
  const int m0 = blockIdx.x * 128;
  const int n0 = blockIdx.y * 64;

  const float4* xg = (const float4*)x;
  for (int i = tid; i < 4096; i += 256) {
    int row = i >> 5, c4 = i & 31;
    float4 v = xg[(size_t)(m0 + row) * 32 + c4];
    *(float4*)&Xs[row * 132 + c4 * 4] = v;
  }
  const float4* wg = (const float4*)W_ih;
  for (int i = tid; i < 2048; i += 256) {
    int row = i >> 5, c4 = i & 31;
    float4 v = wg[(size_t)(n0 + row) * 32 + c4];
    *(float4*)&Ws[row * 132 + c4 * 4] = v;
  }
  __syncthreads();

  const int tx = tid & 15, ty = tid >> 4;
  unsigned long long acc[8][4];
  #pragma unroll
  for (int i = 0; i < 8; i++)
    #pragma unroll
    for (int j = 0; j < 4; j++) acc[i][j] = 0ull;

  #pragma unroll 2
  for (int k = 0; k < 128; k += 4) {
    ulonglong2 xv[8], wv[4];
    #pragma unroll
    for (int i = 0; i < 8; i++) xv[i] = *(const ulonglong2*)&Xs[(ty + i * 16) * 132 + k];
    #pragma unroll
    for (int j = 0; j < 4; j++) wv[j] = *(const ulonglong2*)&Ws[(tx + j * 16) * 132 + k];
    #pragma unroll
    for (int i = 0; i < 8; i++)
      #pragma unroll
      for (int j = 0; j < 4; j++) {
        ffma2(acc[i][j], xv[i].x, wv[j].x);
        ffma2(acc[i][j], xv[i].y, wv[j].y);
      }
  }

  #pragma unroll
  for (int j = 0; j < 4; j++) {
    int n = n0 + tx + j * 16;
    int p = n >> 8, ln = n & 63, rk = (n >> 6) & 3;
    float bias = b_ih[n] + (p < 2 ? b_hh[n] : 0.f);
    int gl = p * 64 + ln;
    #pragma unroll
    for (int i = 0; i < 8; i++) {
      int m = m0 + ty + i * 16;
      int t = m >> 8, b = m & 255;
      size_t addr = (size_t)((((t * 32 + (b >> 3)) * 4 + rk) * 8 + (b & 7))) * 192 + gl;
      g_GI[addr] = pred(acc[i][j]) + bias;
    }
  }
}

// ========================= Phase 2: recurrent scan (256 threads) =========================
__device__ __forceinline__ void stcl64(uint32_t addr, uint32_t rk, unsigned long long v) {
  uint32_t ra;
  asm volatile("mapa.shared::cluster.u32 %0, %1, %2;" : "=r"(ra) : "r"(addr), "r"(rk));
  asm volatile("st.shared::cluster.b64 [%0], %1;" :: "r"(ra), "l"(v) : "memory");
}

// smem float offsets (W pitch 260, H pitch 260)
#define WS_OFF  0       // [192][260] W_hh slice, k-major, pitch 260
#define H_OFF   49920   // 2 x [8][260] double-buffered full h
#define GI_OFF  54080   // [8][192] current gi (r,z overlaid with gh after GEMM)
#define GHN_OFF 55616   // [8][64] gh n-gate
#define BHN_OFF 56128   // [64]
#define WD_OFF  56192   // [256]
#define SM2_FLOATS 56448  // 225792 bytes

__global__ __launch_bounds__(256, 1) __cluster_dims__(4, 1, 1)
void rnn_kernel(const float* __restrict__ gt, const float* __restrict__ W_hh,
                const float* __restrict__ b_hh, const float* __restrict__ W_dec,
                const float* __restrict__ b_dec)
{
  extern __shared__ float sh[];
  float* Ws    = sh + WS_OFF;
  float* Hbuf  = sh + H_OFF;
  float* giS   = sh + GI_OFF;
  float* ghN   = sh + GHN_OFF;
  float* bhhnS = sh + BHN_OFF;
  float* wdecS = sh + WD_OFF;

  const int tid = threadIdx.x;
  const int warp = tid >> 5, lane = tid & 31;
  uint32_t rank; asm("mov.u32 %0, %%cluster_ctarank;" : "=r"(rank));
  const int cl = blockIdx.x >> 2;

  // W_hh slice: local gate gl = p*64+ln  <->  global row p*256+rank*64+ln
  for (int i = tid; i < 12288; i += 256) {
    int j = i >> 6, c4 = i & 63;
    int p = j >> 6, ln = j & 63;
    float4 v = *(const float4*)&W_hh[(size_t)(p * 256 + (int)rank * 64 + ln) * 256 + c4 * 4];
    *(float4*)&Ws[j * 260 + c4 * 4] = v;
  }
  if (tid < 64) bhhnS[tid] = b_hh[512 + (int)rank * 64 + tid];
  wdecS[tid] = W_dec[tid];
  for (int i = tid; i < 4160; i += 256) Hbuf[i] = 0.f;
  {
    const float2* src = (const float2*)(g_GI + (size_t)(cl * 4 + (int)rank) * 1536);
    float2* d = (float2*)giS;
    d[tid] = src[tid]; d[tid + 256] = src[tid + 256]; d[tid + 512] = src[tid + 512];
  }
  const float bdec = b_dec[0];
  double lacc = 0.0;
  __syncthreads();
  asm volatile("barrier.cluster.arrive.aligned;" ::: "memory");
  asm volatile("barrier.cluster.wait.aligned;" ::: "memory");

  // Conflict-free mapping: warp covers 8 gate-triples (4-way bcast w) x 4 brow-pairs (8-way bcast h)
  // W units 3*jt mod 8 distinct over jt=0..7 ; H units 2*bp mod 8 distinct over bp=0..3
  const int jt = (warp << 3) + (lane & 7);   // triple 0..63
  const int bp = lane >> 3;                  // brow-pair 0..3
  const int b0 = bp << 1;
  const int g0 = jt * 3;                     // gates g0..g0+2
  const float* W0 = Ws + g0 * 260;
  const float* W1 = W0 + 260;
  const float* W2 = W0 + 520;

  for (int s = 0; s < TSTEPS; s++) {
    const float* Hr = Hbuf + (s & 1) * 2080;
    float* Hw = Hbuf + ((s + 1) & 1) * 2080;

    float gtv = 0.f;
    if (warp < 2) gtv = gt[(s + 1) * 256 + (cl << 3) + ((int)rank << 1) + warp];

    float2 p0, p1, p2;
    if (s + 1 < TSTEPS) {
      const float2* ns = (const float2*)(g_GI + (size_t)(((s + 1) * 32 + cl) * 4 + (int)rank) * 1536);
      p0 = ns[tid]; p1 = ns[tid + 256]; p2 = ns[tid + 512];
    }

    // ---- GEMM (packed f32x2): gh[8][192]; r,z accs init from gi ----
    unsigned long long a00 = pk2((g0     < 128) ? giS[b0 * 192 + g0    ] : 0.f, 0.f);
    unsigned long long a01 = pk2((g0 + 1 < 128) ? giS[b0 * 192 + g0 + 1] : 0.f, 0.f);
    unsigned long long a02 = pk2((g0 + 2 < 128) ? giS[b0 * 192 + g0 + 2] : 0.f, 0.f);
    unsigned long long a10 = pk2((g0     < 128) ? giS[(b0 + 1) * 192 + g0    ] : 0.f, 0.f);
    unsigned long long a11 = pk2((g0 + 1 < 128) ? giS[(b0 + 1) * 192 + g0 + 1] : 0.f, 0.f);
    unsigned long long a12 = pk2((g0 + 2 < 128) ? giS[(b0 + 1) * 192 + g0 + 2] : 0.f, 0.f);

    const float* H0 = Hr + b0 * 260;
    const float* H1 = H0 + 260;
    #pragma unroll 16
    for (int k = 0; k < 256; k += 4) {
      ulonglong2 h0 = *(const ulonglong2*)(H0 + k);
      ulonglong2 h1 = *(const ulonglong2*)(H1 + k);
      ulonglong2 w0 = *(const ulonglong2*)(W0 + k);
      ulonglong2 w1 = *(const ulonglong2*)(W1 + k);
      ulonglong2 w2 = *(const ulonglong2*)(W2 + k);
      ffma2(a00, h0.x, w0.x); ffma2(a00, h0.y, w0.y);
      ffma2(a01, h0.x, w1.x); ffma2(a01, h0.y, w1.y);
      ffma2(a02, h0.x, w2.x); ffma2(a02, h0.y, w2.y);
      ffma2(a10, h1.x, w0.x); ffma2(a10, h1.y, w0.y);
      ffma2(a11, h1.x, w1.x); ffma2(a11, h1.y, w1.y);
      ffma2(a12, h1.x, w2.x); ffma2(a12, h1.y, w2.y);
    }
    float f00 = pred(a00), f01 = pred(a01), f02 = pred(a02);
    float f10 = pred(a10), f11 = pred(a11), f12 = pred(a12);
    if (g0     < 128) giS[b0 * 192 + g0    ] = f00; else ghN[(b0 << 6) + g0     - 128] = f00;
    if (g0 + 1 < 128) giS[b0 * 192 + g0 + 1] = f01; else ghN[(b0 << 6) + g0 + 1 - 128] = f01;
    if (g0 + 2 < 128) giS[b0 * 192 + g0 + 2] = f02; else ghN[(b0 << 6) + g0 + 2 - 128] = f02;
    if (g0     < 128) giS[(b0 + 1) * 192 + g0    ] = f10; else ghN[((b0 + 1) << 6) + g0     - 128] = f10;
    if (g0 + 1 < 128) giS[(b0 + 1) * 192 + g0 + 1] = f11; else ghN[((b0 + 1) << 6) + g0 + 1 - 128] = f11;
    if (g0 + 2 < 128) giS[(b0 + 1) * 192 + g0 + 2] = f12; else ghN[((b0 + 1) << 6) + g0 + 2 - 128] = f12;
    __syncthreads();

    // ---- gates + h_new: 256 threads x 2 elements (cols [rank*64, rank*64+64)) ----
    {
      int e = tid << 1;
      int b = e >> 6, c = e & 63;
      int colb = ((int)rank << 6) + c;
      float hv[2];
      #pragma unroll
      for (int u = 0; u < 2; u++) {
        int cc = c + u;
        float pr  = giS[b * 192 + cc];
        float pz  = giS[b * 192 + 64 + cc];
        float gin = giS[b * 192 + 128 + cc];
        float ghn = ghN[(b << 6) + cc] + bhhnS[cc];
        float hp  = Hr[b * 260 + colb + u];
        float rr = __fdividef(1.f, 1.f + __expf(-pr));
        float zz = __fdividef(1.f, 1.f + __expf(-pz));
        float e2 = __expf(2.f * fmaf(rr, ghn, gin));
        float nn = 1.f - __fdividef(2.f, e2 + 1.f);
        hv[u] = (1.f - zz) * nn + zz * hp;
      }
      float* dst = &Hw[b * 260 + colb];
      dst[0] = hv[0]; dst[1] = hv[1];
      unsigned long long pv = pk2(hv[0], hv[1]);
      uint32_t a0 = (uint32_t)__cvta_generic_to_shared(dst);
      stcl64(a0, (rank + 1) & 3, pv);
      stcl64(a0, (rank + 2) & 3, pv);
      stcl64(a0, (rank + 3) & 3, pv);
    }
    __syncthreads();
    asm volatile("barrier.cluster.arrive.aligned;" ::: "memory");
    if (s + 1 < TSTEPS) {  // stage next gi inside the arrive->wait window
      float2* d = (float2*)giS;
      d[tid] = p0; d[tid + 256] = p1; d[tid + 512] = p2;
    }
    asm volatile("barrier.cluster.wait.aligned;" ::: "memory");

    // ---- decode + BCE: CTA rank handles local brows {2r, 2r+1} ----
    if (warp < 2) {
      const float* hrow = Hw + (((int)rank << 1) + warp) * 260;
      float part = 0.f;
      #pragma unroll
      for (int q = 0; q < 8; q++) part = fmaf(hrow[lane + q * 32], wdecS[lane + q * 32], part);
      #pragma unroll
      for (int o = 16; o > 0; o >>= 1) part += __shfl_xor_sync(0xffffffffu, part, o);
      if (lane == 0) {
        float L = part + bdec;
        float tl = log1pf(expf(-fabsf(L)));
        float lsp = fminf(L, 0.f) - tl;
        float lsm = fminf(-L, 0.f) - tl;
        lacc -= (double)(gtv * lsp + (1.f - gtv) * lsm);
      }
    }
  }

  if (warp < 2 && lane == 0)
    g_loss[(cl << 3) + ((int)rank << 1) + warp] = lacc;
}

// ========================= Phase 3: deterministic reduce =========================
__global__ void reduce_kernel(float* out) {
  double s = 0.0;
  for (int i = 0; i < 256; i++) s += g_loss[i];
  out[0] = (float)s;
}

extern "C" void kernel_launch(void* const* d_in, const int* in_sizes, int n_in,
                              void* d_out, int out_size) {
  (void)in_sizes; (void)n_in; (void)out_size;
  const float* x     = (const float*)d_in[0];
  const float* gt    = (const float*)d_in[1];
  const float* W_ih  = (const float*)d_in[2];
  const float* W_hh  = (const float*)d_in[3];
  const float* b_ih  = (const float*)d_in[4];
  const float* b_hh  = (const float*)d_in[5];
  const float* W_dec = (const float*)d_in[6];
  const float* b_dec = (const float*)d_in[7];

  cudaFuncSetAttribute(gi_kernel,  cudaFuncAttributeMaxDynamicSharedMemorySize, 101376);
  cudaFuncSetAttribute(rnn_kernel, cudaFuncAttributeMaxDynamicSharedMemorySize, SM2_FLOATS * 4);

  dim3 g1(1022, 12);
  gi_kernel<<<g1, 256, 101376>>>(x, W_ih, b_ih, b_hh);
  rnn_kernel<<<128, 256, SM2_FLOATS * 4>>>(gt, W_hh, b_hh, W_dec, b_dec);
  reduce_kernel<<<1, 1>>>((float*)d_out);
}